// round 7
// baseline (speedup 1.0000x reference)
#include <cuda_runtime.h>
#include <cstdint>

// Problem constants (match reference_code)
#define N0c 200000
#define N1c 50000
#define N2c 12500
#define N3c 3200
#define E0c 500000
#define E1c 125000
#define E2c 32000

// ---------------- scratch (static device globals; no allocations) ----------------
__device__ int g_deg0[N1c]; __device__ int g_off0[N1c + 1]; __device__ int g_cur0[N1c]; __device__ int g_esrc0[E0c];
__device__ int g_deg1[N2c]; __device__ int g_off1[N2c + 1]; __device__ int g_cur1[N2c]; __device__ int g_esrc1[E1c];
__device__ int g_deg2[N3c]; __device__ int g_off2[N3c + 1]; __device__ int g_cur2[N3c]; __device__ int g_esrc2[E2c];
__device__ float g_h1[(size_t)N1c * 256];
__device__ float g_h2[(size_t)N2c * 256];

__device__ __forceinline__ uint32_t f2tf32(float f) {
    uint32_t u;
    asm("cvt.rna.tf32.f32 %0, %1;" : "=r"(u) : "f"(f));
    return u;
}

// ---------------- batched CSR build (all 3 layers in one pass each) ----------------
__global__ void zero3_kernel() {
    int i = blockIdx.x * blockDim.x + threadIdx.x;
    if (i < N1c) g_deg0[i] = 0;
    else if (i < N1c + N2c) g_deg1[i - N1c] = 0;
    else if (i < N1c + N2c + N3c) g_deg2[i - N1c - N2c] = 0;
}

__global__ void hist3_kernel(const int* __restrict__ d0, const int* __restrict__ d1,
                             const int* __restrict__ d2) {
    int e = blockIdx.x * blockDim.x + threadIdx.x;
    if (e < E0c) atomicAdd(&g_deg0[d0[e]], 1);
    else if (e < E0c + E1c) atomicAdd(&g_deg1[d1[e - E0c]], 1);
    else if (e < E0c + E1c + E2c) atomicAdd(&g_deg2[d2[e - E0c - E1c]], 1);
}

// One block per layer; chunked one-pass scan (1024 threads).
__global__ void scan3_kernel() {
    const int T = 1024;
    __shared__ int wsum[32];
    int layer = blockIdx.x;
    int n = (layer == 0) ? N1c : (layer == 1) ? N2c : N3c;
    int E = (layer == 0) ? E0c : (layer == 1) ? E1c : E2c;
    int* deg = (layer == 0) ? g_deg0 : (layer == 1) ? g_deg1 : g_deg2;
    int* off = (layer == 0) ? g_off0 : (layer == 1) ? g_off1 : g_off2;
    int* cur = (layer == 0) ? g_cur0 : (layer == 1) ? g_cur1 : g_cur2;

    int tid = threadIdx.x, lane = tid & 31, wid = tid >> 5;
    int chunk = (n + T - 1) / T;
    int beg = min(tid * chunk, n), end = min(beg + chunk, n);

    int sum = 0;
    for (int i = beg; i < end; i++) sum += deg[i];

    int s = sum;
    #pragma unroll
    for (int o = 1; o < 32; o <<= 1) {
        int t = __shfl_up_sync(0xffffffffu, s, o);
        if (lane >= o) s += t;
    }
    if (lane == 31) wsum[wid] = s;
    __syncthreads();
    if (wid == 0) {
        int ws = wsum[lane];
        #pragma unroll
        for (int o = 1; o < 32; o <<= 1) {
            int t = __shfl_up_sync(0xffffffffu, ws, o);
            if (lane >= o) ws += t;
        }
        wsum[lane] = ws;
    }
    __syncthreads();
    int excl = s - sum + ((wid > 0) ? wsum[wid - 1] : 0);

    int run = excl;
    for (int i = beg; i < end; i++) {
        int d = deg[i];
        off[i] = run;
        cur[i] = run;
        run += d;
    }
    if (tid == 0) off[n] = E;
}

__global__ void bucket3_kernel(const int* __restrict__ s0, const int* __restrict__ d0,
                               const int* __restrict__ s1, const int* __restrict__ d1,
                               const int* __restrict__ s2, const int* __restrict__ d2) {
    int e = blockIdx.x * blockDim.x + threadIdx.x;
    if (e < E0c) {
        int p = atomicAdd(&g_cur0[d0[e]], 1);
        g_esrc0[p] = s0[e];
    } else if (e < E0c + E1c) {
        int i = e - E0c;
        int p = atomicAdd(&g_cur1[d1[i]], 1);
        g_esrc1[p] = s1[i];
    } else if (e < E0c + E1c + E2c) {
        int i = e - E0c - E1c;
        int p = atomicAdd(&g_cur2[d2[i]], 1);
        g_esrc2[p] = s2[i];
    }
}

// ---------------- fused aggregation + dual-A tf32 GEMM ----------------
// Per block: 128 target rows x N cols.  out = act( mean@Wl^T + x_tgt@Wr^T + b )
// Phase 1: warp-per-node gather-mean -> As0 smem (tf32, stride D+4).
// Phase 2: K-loop over 2D in BK=32 steps; first D from resident As0 (no staging),
// second D stages x_tgt tiles (At) from global; B (weights) staged per tile.
// 512 threads = 16 warps (2m x 8n), warp tile 64 x (N/8), m16n8k8 tf32 mma.

template <int D, int NFRAG>   // NFRAG = N/64 per-warp n-fragments; N = NFRAG*64
__global__ void __launch_bounds__(512, 1) sage_fused(
    const float* __restrict__ X,
    const float* __restrict__ Wl, const float* __restrict__ Wr,
    const float* __restrict__ bias, float* __restrict__ out,
    const int* __restrict__ off, const int* __restrict__ esrc,
    int M, int relu)
{
    const int N = NFRAG * 64;
    const int LDA = D + 4;
    extern __shared__ uint32_t sm[];
    uint32_t* As0 = sm;                  // 128 * LDA   (tf32 mean)
    uint32_t* At  = As0 + 128 * LDA;     // 128 * 36    (x_tgt k-tile)
    uint32_t* Bs  = At + 128 * 36;       // N * 36      (weight k-tile)

    int tid = threadIdx.x, lane = tid & 31, wid = tid >> 5;
    int rowBase = blockIdx.x * 128;

    // ---- Phase 1: gather-mean into As0 ----
    const int NF4 = D / 128;   // float4s per lane per row (1 or 2)
    for (int rr = wid; rr < 128; rr += 16) {
        int node = rowBase + rr;
        float acc[4 * NF4];
        #pragma unroll
        for (int i = 0; i < 4 * NF4; i++) acc[i] = 0.f;
        if (node < M) {
            int beg = off[node], end = off[node + 1];
            int e = beg;
            for (; e + 1 < end; e += 2) {
                const float4* r0 = (const float4*)(X + (size_t)esrc[e] * D);
                const float4* r1 = (const float4*)(X + (size_t)esrc[e + 1] * D);
                #pragma unroll
                for (int i = 0; i < NF4; i++) {
                    float4 v0 = r0[lane + 32 * i];
                    float4 v1 = r1[lane + 32 * i];
                    acc[4 * i + 0] += v0.x + v1.x;
                    acc[4 * i + 1] += v0.y + v1.y;
                    acc[4 * i + 2] += v0.z + v1.z;
                    acc[4 * i + 3] += v0.w + v1.w;
                }
            }
            if (e < end) {
                const float4* r0 = (const float4*)(X + (size_t)esrc[e] * D);
                #pragma unroll
                for (int i = 0; i < NF4; i++) {
                    float4 v0 = r0[lane + 32 * i];
                    acc[4 * i + 0] += v0.x;
                    acc[4 * i + 1] += v0.y;
                    acc[4 * i + 2] += v0.z;
                    acc[4 * i + 3] += v0.w;
                }
            }
            float inv = 1.f / (float)max(end - beg, 1);
            #pragma unroll
            for (int i = 0; i < 4 * NF4; i++) acc[i] *= inv;
        }
        #pragma unroll
        for (int i = 0; i < NF4; i++) {
            uint4 u;
            u.x = f2tf32(acc[4 * i + 0]);
            u.y = f2tf32(acc[4 * i + 1]);
            u.z = f2tf32(acc[4 * i + 2]);
            u.w = f2tf32(acc[4 * i + 3]);
            *(uint4*)&As0[rr * LDA + 4 * lane + 128 * i] = u;
        }
    }
    __syncthreads();

    // ---- Phase 2: GEMM ----
    int wm = wid & 1;        // 0..1  -> 64-row half
    int wn = wid >> 1;       // 0..7  -> (N/8)-col strip
    int g = lane >> 2, t = lane & 3;

    float facc[4][NFRAG][4];
    #pragma unroll
    for (int i = 0; i < 4; i++)
        #pragma unroll
        for (int j = 0; j < NFRAG; j++)
            #pragma unroll
            for (int r = 0; r < 4; r++) facc[i][j][r] = 0.f;

    const int NT = (2 * D) / 32;

    for (int it = 0; it < NT; it++) {
        int kt = it * 32;
        bool second = (kt >= D);
        const float* W = second ? Wr : Wl;
        int kk = second ? kt - D : kt;

        // stage B tile: N rows x 32 k (cvt tf32 at STS)
        #pragma unroll
        for (int s = 0; s < N / 64; s++) {
            int idx = tid + 512 * s;            // < N*8
            int r = idx >> 3, kg = (idx & 7) * 4;
            float4 v = *(const float4*)(W + (size_t)r * D + kk + kg);
            uint4 u;
            u.x = f2tf32(v.x); u.y = f2tf32(v.y); u.z = f2tf32(v.z); u.w = f2tf32(v.w);
            *(uint4*)&Bs[r * 36 + kg] = u;
        }
        // stage x_tgt tile for second half
        if (second) {
            #pragma unroll
            for (int s = 0; s < 2; s++) {
                int idx = tid + 512 * s;        // < 1024 = 128*8
                int r = idx >> 3, kg = (idx & 7) * 4;
                int node = rowBase + r;
                float4 v = make_float4(0.f, 0.f, 0.f, 0.f);
                if (node < M) v = *(const float4*)(X + (size_t)node * D + kk + kg);
                uint4 u;
                u.x = f2tf32(v.x); u.y = f2tf32(v.y); u.z = f2tf32(v.z); u.w = f2tf32(v.w);
                *(uint4*)&At[r * 36 + kg] = u;
            }
        }
        __syncthreads();

        const uint32_t* Aptr = second ? At : (As0 + kt);
        const int lda = second ? 36 : LDA;

        #pragma unroll
        for (int ks = 0; ks < 32; ks += 8) {
            uint32_t af[4][4];
            #pragma unroll
            for (int mi = 0; mi < 4; mi++) {
                int m = wm * 64 + mi * 16;
                af[mi][0] = Aptr[(m + g)     * lda + ks + t];
                af[mi][1] = Aptr[(m + g + 8) * lda + ks + t];
                af[mi][2] = Aptr[(m + g)     * lda + ks + t + 4];
                af[mi][3] = Aptr[(m + g + 8) * lda + ks + t + 4];
            }
            uint32_t bf[NFRAG][2];
            #pragma unroll
            for (int ni = 0; ni < NFRAG; ni++) {
                int n = wn * (NFRAG * 8) + ni * 8;
                bf[ni][0] = Bs[(n + g) * 36 + ks + t];
                bf[ni][1] = Bs[(n + g) * 36 + ks + t + 4];
            }
            #pragma unroll
            for (int mi = 0; mi < 4; mi++)
                #pragma unroll
                for (int ni = 0; ni < NFRAG; ni++) {
                    asm volatile(
                        "mma.sync.aligned.m16n8k8.row.col.f32.tf32.tf32.f32 "
                        "{%0,%1,%2,%3}, {%4,%5,%6,%7}, {%8,%9}, {%0,%1,%2,%3};"
                        : "+f"(facc[mi][ni][0]), "+f"(facc[mi][ni][1]),
                          "+f"(facc[mi][ni][2]), "+f"(facc[mi][ni][3])
                        : "r"(af[mi][0]), "r"(af[mi][1]), "r"(af[mi][2]), "r"(af[mi][3]),
                          "r"(bf[ni][0]), "r"(bf[ni][1]));
                }
        }
        __syncthreads();
    }

    // ---- epilogue: bias + optional relu ----
    #pragma unroll
    for (int mi = 0; mi < 4; mi++) {
        #pragma unroll
        for (int ni = 0; ni < NFRAG; ni++) {
            int col = wn * (NFRAG * 8) + ni * 8 + t * 2;
            float b0v = bias[col], b1v = bias[col + 1];
            int row0 = rowBase + wm * 64 + mi * 16 + g;
            if (row0 < M) {
                float2 o;
                o.x = facc[mi][ni][0] + b0v;
                o.y = facc[mi][ni][1] + b1v;
                if (relu) { o.x = fmaxf(o.x, 0.f); o.y = fmaxf(o.y, 0.f); }
                *(float2*)(out + (size_t)row0 * N + col) = o;
            }
            int row1 = row0 + 8;
            if (row1 < M) {
                float2 o;
                o.x = facc[mi][ni][2] + b0v;
                o.y = facc[mi][ni][3] + b1v;
                if (relu) { o.x = fmaxf(o.x, 0.f); o.y = fmaxf(o.y, 0.f); }
                *(float2*)(out + (size_t)row1 * N + col) = o;
            }
        }
    }
}

// smem bytes per instantiation
static inline int fused_smem(int D, int N) {
    return (128 * (D + 4) + 128 * 36 + N * 36) * 4;
}

extern "C" void kernel_launch(void* const* d_in, const int* in_sizes, int n_in,
                              void* d_out, int out_size)
{
    const float* x    = (const float*)d_in[0];
    const int*   src0 = (const int*)d_in[1];
    const int*   dst0 = (const int*)d_in[2];
    const int*   src1 = (const int*)d_in[3];
    const int*   dst1 = (const int*)d_in[4];
    const int*   src2 = (const int*)d_in[5];
    const int*   dst2 = (const int*)d_in[6];
    const float* wl0  = (const float*)d_in[7];
    const float* wr0  = (const float*)d_in[8];
    const float* b0   = (const float*)d_in[9];
    const float* wl1  = (const float*)d_in[10];
    const float* wr1  = (const float*)d_in[11];
    const float* b1   = (const float*)d_in[12];
    const float* wl2  = (const float*)d_in[13];
    const float* wr2  = (const float*)d_in[14];
    const float* b2   = (const float*)d_in[15];
    float* out = (float*)d_out;

    int sm0 = fused_smem(128, 256);
    int sm1 = fused_smem(256, 256);
    int sm2 = fused_smem(256, 128);
    cudaFuncSetAttribute((const void*)sage_fused<128, 4>,
                         cudaFuncAttributeMaxDynamicSharedMemorySize, sm0);
    cudaFuncSetAttribute((const void*)sage_fused<256, 4>,
                         cudaFuncAttributeMaxDynamicSharedMemorySize, sm1);
    cudaFuncSetAttribute((const void*)sage_fused<256, 2>,
                         cudaFuncAttributeMaxDynamicSharedMemorySize, sm2);

    float *h1, *h2;
    cudaGetSymbolAddress((void**)&h1, g_h1);
    cudaGetSymbolAddress((void**)&h2, g_h2);
    int *off0, *off1, *off2, *es0, *es1, *es2;
    cudaGetSymbolAddress((void**)&off0, g_off0);
    cudaGetSymbolAddress((void**)&off1, g_off1);
    cudaGetSymbolAddress((void**)&off2, g_off2);
    cudaGetSymbolAddress((void**)&es0, g_esrc0);
    cudaGetSymbolAddress((void**)&es1, g_esrc1);
    cudaGetSymbolAddress((void**)&es2, g_esrc2);

    // Batched CSR build for all 3 layers (feature-independent)
    const int NTOT = N1c + N2c + N3c;
    const int ETOT = E0c + E1c + E2c;
    zero3_kernel<<<(NTOT + 255) / 256, 256>>>();
    hist3_kernel<<<(ETOT + 255) / 256, 256>>>(dst0, dst1, dst2);
    scan3_kernel<<<3, 1024>>>();
    bucket3_kernel<<<(ETOT + 255) / 256, 256>>>(src0, dst0, src1, dst1, src2, dst2);

    // Layer 0: x (N0 x 128) -> h1 (N1 x 256), relu
    sage_fused<128, 4><<<(N1c + 127) / 128, 512, sm0>>>(
        x, wl0, wr0, b0, h1, off0, es0, N1c, 1);
    // Layer 1: h1 (N1 x 256) -> h2 (N2 x 256), relu
    sage_fused<256, 4><<<(N2c + 127) / 128, 512, sm1>>>(
        h1, wl1, wr1, b1, h2, off1, es1, N2c, 1);
    // Layer 2: h2 (N2 x 256) -> out (N3 x 128), no relu
    sage_fused<256, 2><<<(N3c + 127) / 128, 512, sm2>>>(
        h2, wl2, wr2, b2, out, off2, es2, N3c, 0);
}

// round 8
// speedup vs baseline: 1.1369x; 1.1369x over previous
#include <cuda_runtime.h>
#include <cstdint>

// Problem constants (match reference_code)
#define N0c 200000
#define N1c 50000
#define N2c 12500
#define N3c 3200
#define E0c 500000
#define E1c 125000
#define E2c 32000
#define DINc 128
#define DHc 256
#define DOUTc 128

// ---------------- scratch (static device globals; no allocations) ----------------
__device__ float g_mean[(size_t)N1c * DHc];
__device__ float g_h1[(size_t)N1c * DHc];
__device__ float g_h2[(size_t)N2c * DHc];
__device__ int g_deg0[N1c]; __device__ int g_off0[N1c + 1]; __device__ int g_cur0[N1c]; __device__ int g_esrc0[E0c];
__device__ int g_deg1[N2c]; __device__ int g_off1[N2c + 1]; __device__ int g_cur1[N2c]; __device__ int g_esrc1[E1c];
__device__ int g_deg2[N3c]; __device__ int g_off2[N3c + 1]; __device__ int g_cur2[N3c]; __device__ int g_esrc2[E2c];

// ---------------- batched CSR build (all 3 layers in one pass each) ----------------
__global__ void zero3_kernel() {
    int i = blockIdx.x * blockDim.x + threadIdx.x;
    if (i < N1c) g_deg0[i] = 0;
    else if (i < N1c + N2c) g_deg1[i - N1c] = 0;
    else if (i < N1c + N2c + N3c) g_deg2[i - N1c - N2c] = 0;
}

__global__ void hist3_kernel(const int* __restrict__ d0, const int* __restrict__ d1,
                             const int* __restrict__ d2) {
    int e = blockIdx.x * blockDim.x + threadIdx.x;
    if (e < E0c) atomicAdd(&g_deg0[d0[e]], 1);
    else if (e < E0c + E1c) atomicAdd(&g_deg1[d1[e - E0c]], 1);
    else if (e < E0c + E1c + E2c) atomicAdd(&g_deg2[d2[e - E0c - E1c]], 1);
}

// One block per layer; chunked one-pass scan (1024 threads).
__global__ void scan3_kernel() {
    const int T = 1024;
    __shared__ int wsum[32];
    int layer = blockIdx.x;
    int n = (layer == 0) ? N1c : (layer == 1) ? N2c : N3c;
    int E = (layer == 0) ? E0c : (layer == 1) ? E1c : E2c;
    int* deg = (layer == 0) ? g_deg0 : (layer == 1) ? g_deg1 : g_deg2;
    int* off = (layer == 0) ? g_off0 : (layer == 1) ? g_off1 : g_off2;
    int* cur = (layer == 0) ? g_cur0 : (layer == 1) ? g_cur1 : g_cur2;

    int tid = threadIdx.x, lane = tid & 31, wid = tid >> 5;
    int chunk = (n + T - 1) / T;
    int beg = min(tid * chunk, n), end = min(beg + chunk, n);

    int sum = 0;
    for (int i = beg; i < end; i++) sum += deg[i];

    int s = sum;
    #pragma unroll
    for (int o = 1; o < 32; o <<= 1) {
        int t = __shfl_up_sync(0xffffffffu, s, o);
        if (lane >= o) s += t;
    }
    if (lane == 31) wsum[wid] = s;
    __syncthreads();
    if (wid == 0) {
        int ws = wsum[lane];
        #pragma unroll
        for (int o = 1; o < 32; o <<= 1) {
            int t = __shfl_up_sync(0xffffffffu, ws, o);
            if (lane >= o) ws += t;
        }
        wsum[lane] = ws;
    }
    __syncthreads();
    int excl = s - sum + ((wid > 0) ? wsum[wid - 1] : 0);

    int run = excl;
    for (int i = beg; i < end; i++) {
        int d = deg[i];
        off[i] = run;
        cur[i] = run;
        run += d;
    }
    if (tid == 0) off[n] = E;
}

__global__ void bucket3_kernel(const int* __restrict__ s0, const int* __restrict__ d0,
                               const int* __restrict__ s1, const int* __restrict__ d1,
                               const int* __restrict__ s2, const int* __restrict__ d2) {
    int e = blockIdx.x * blockDim.x + threadIdx.x;
    if (e < E0c) {
        int p = atomicAdd(&g_cur0[d0[e]], 1);
        g_esrc0[p] = s0[e];
    } else if (e < E0c + E1c) {
        int i = e - E0c;
        int p = atomicAdd(&g_cur1[d1[i]], 1);
        g_esrc1[p] = s1[i];
    } else if (e < E0c + E1c + E2c) {
        int i = e - E0c - E1c;
        int p = atomicAdd(&g_cur2[d2[i]], 1);
        g_esrc2[p] = s2[i];
    }
}

// ---------------- aggregation: warp per target node, register accumulation ----------------
template <int D>
__global__ void aggregate_kernel(const float* __restrict__ X, float* __restrict__ mean,
                                 const int* __restrict__ off, const int* __restrict__ esrc,
                                 int n_tgt) {
    int w = (blockIdx.x * blockDim.x + threadIdx.x) >> 5;
    int lane = threadIdx.x & 31;
    if (w >= n_tgt) return;
    int beg = off[w], end = off[w + 1];
    float acc[D / 32];
    #pragma unroll
    for (int i = 0; i < D / 32; i++) acc[i] = 0.f;
    int e = beg;
    for (; e + 1 < end; e += 2) {
        int s0 = esrc[e], s1 = esrc[e + 1];
        const float4* r0 = (const float4*)(X + (size_t)s0 * D);
        const float4* r1 = (const float4*)(X + (size_t)s1 * D);
        #pragma unroll
        for (int i = 0; i < D / 128; i++) {
            float4 v0 = r0[lane + 32 * i];
            float4 v1 = r1[lane + 32 * i];
            acc[4 * i + 0] += v0.x + v1.x;
            acc[4 * i + 1] += v0.y + v1.y;
            acc[4 * i + 2] += v0.z + v1.z;
            acc[4 * i + 3] += v0.w + v1.w;
        }
    }
    if (e < end) {
        const float4* row = (const float4*)(X + (size_t)esrc[e] * D);
        #pragma unroll
        for (int i = 0; i < D / 128; i++) {
            float4 v = row[lane + 32 * i];
            acc[4 * i + 0] += v.x;
            acc[4 * i + 1] += v.y;
            acc[4 * i + 2] += v.z;
            acc[4 * i + 3] += v.w;
        }
    }
    float inv = 1.f / (float)max(end - beg, 1);
    float4* mrow = (float4*)(mean + (size_t)w * D);
    #pragma unroll
    for (int i = 0; i < D / 128; i++) {
        float4 o;
        o.x = acc[4 * i + 0] * inv;
        o.y = acc[4 * i + 1] * inv;
        o.z = acc[4 * i + 2] * inv;
        o.w = acc[4 * i + 3] * inv;
        mrow[lane + 32 * i] = o;
    }
}

// ---------------- tf32 tensor-core fused dual-A GEMM (R2 schedule) ----------------
// out = act( mean@Wl^T + Xtgt@Wr^T + b )
// Block tile 128x128, BK=32, 256 threads = 8 warps (2m x 4n), warp tile 64x32
// (4x4 m16n8k8 tf32 mma). Synchronous single buffer, cvt once at STS time.

__device__ __forceinline__ uint32_t f2tf32(float f) {
    uint32_t u;
    asm("cvt.rna.tf32.f32 %0, %1;" : "=r"(u) : "f"(f));
    return u;
}

__global__ void __launch_bounds__(256) sage_gemm_tf32(
    const float* __restrict__ A0, const float* __restrict__ A1,
    const float* __restrict__ Wl, const float* __restrict__ Wr,
    const float* __restrict__ bias, float* __restrict__ out,
    int M, int N, int D, int relu)
{
    const int BM = 128, BK = 32;
    const int LDS_ = BK + 4;  // 36 words -> conflict-free fragment reads
    __shared__ uint32_t As[BM * LDS_];
    __shared__ uint32_t Bs[BM * LDS_];

    int tid = threadIdx.x;
    int lane = tid & 31, wid = tid >> 5;
    int wm = wid & 1;        // 0..1  -> 64-row half
    int wn = wid >> 1;       // 0..3  -> 32-col strip
    int g = lane >> 2, t = lane & 3;

    int rowBase = blockIdx.x * BM, colBase = blockIdx.y * BM;

    float acc[4][4][4];
    #pragma unroll
    for (int i = 0; i < 4; i++)
        #pragma unroll
        for (int j = 0; j < 4; j++)
            #pragma unroll
            for (int r = 0; r < 4; r++) acc[i][j][r] = 0.f;

    int ldr = tid >> 3;          // 0..31 (row within 32-row chunk)
    int ldc = (tid & 7) * 4;     // 0,4,...,28 (k offset)

    for (int kt = 0; kt < 2 * D; kt += BK) {
        const float* A = (kt < D) ? A0 : A1;
        const float* W = (kt < D) ? Wl : Wr;
        int kk = (kt < D) ? kt : (kt - D);

        #pragma unroll
        for (int s = 0; s < 4; s++) {
            int r = ldr + s * 32;
            int grow = rowBase + r;
            float4 v = make_float4(0.f, 0.f, 0.f, 0.f);
            if (grow < M) v = *(const float4*)(A + (size_t)grow * D + kk + ldc);
            uint4 ua;
            ua.x = f2tf32(v.x); ua.y = f2tf32(v.y); ua.z = f2tf32(v.z); ua.w = f2tf32(v.w);
            *(uint4*)&As[r * LDS_ + ldc] = ua;
            float4 w = *(const float4*)(W + (size_t)(colBase + r) * D + kk + ldc);
            uint4 ub;
            ub.x = f2tf32(w.x); ub.y = f2tf32(w.y); ub.z = f2tf32(w.z); ub.w = f2tf32(w.w);
            *(uint4*)&Bs[r * LDS_ + ldc] = ub;
        }
        __syncthreads();

        #pragma unroll
        for (int ks = 0; ks < BK; ks += 8) {
            uint32_t af[4][4];
            #pragma unroll
            for (int mi = 0; mi < 4; mi++) {
                int m = wm * 64 + mi * 16;
                af[mi][0] = As[(m + g)     * LDS_ + ks + t];
                af[mi][1] = As[(m + g + 8) * LDS_ + ks + t];
                af[mi][2] = As[(m + g)     * LDS_ + ks + t + 4];
                af[mi][3] = As[(m + g + 8) * LDS_ + ks + t + 4];
            }
            uint32_t bf[4][2];
            #pragma unroll
            for (int ni = 0; ni < 4; ni++) {
                int n = wn * 32 + ni * 8;
                bf[ni][0] = Bs[(n + g) * LDS_ + ks + t];
                bf[ni][1] = Bs[(n + g) * LDS_ + ks + t + 4];
            }
            #pragma unroll
            for (int mi = 0; mi < 4; mi++)
                #pragma unroll
                for (int ni = 0; ni < 4; ni++) {
                    asm volatile(
                        "mma.sync.aligned.m16n8k8.row.col.f32.tf32.tf32.f32 "
                        "{%0,%1,%2,%3}, {%4,%5,%6,%7}, {%8,%9}, {%0,%1,%2,%3};"
                        : "+f"(acc[mi][ni][0]), "+f"(acc[mi][ni][1]),
                          "+f"(acc[mi][ni][2]), "+f"(acc[mi][ni][3])
                        : "r"(af[mi][0]), "r"(af[mi][1]), "r"(af[mi][2]), "r"(af[mi][3]),
                          "r"(bf[ni][0]), "r"(bf[ni][1]));
                }
        }
        __syncthreads();
    }

    // epilogue: bias + optional relu
    #pragma unroll
    for (int mi = 0; mi < 4; mi++) {
        #pragma unroll
        for (int ni = 0; ni < 4; ni++) {
            int col = colBase + wn * 32 + ni * 8 + t * 2;
            float b0v = bias[col], b1v = bias[col + 1];
            int row0 = rowBase + wm * 64 + mi * 16 + g;
            if (row0 < M) {
                float2 o;
                o.x = acc[mi][ni][0] + b0v;
                o.y = acc[mi][ni][1] + b1v;
                if (relu) { o.x = fmaxf(o.x, 0.f); o.y = fmaxf(o.y, 0.f); }
                *(float2*)(out + (size_t)row0 * N + col) = o;
            }
            int row1 = row0 + 8;
            if (row1 < M) {
                float2 o;
                o.x = acc[mi][ni][2] + b0v;
                o.y = acc[mi][ni][3] + b1v;
                if (relu) { o.x = fmaxf(o.x, 0.f); o.y = fmaxf(o.y, 0.f); }
                *(float2*)(out + (size_t)row1 * N + col) = o;
            }
        }
    }
}

// ---------------- host-side layer driver (compute only; CSR done up front) ----------------
static void run_layer(const float* X, const int* off, const int* esrc,
                      int n_tgt, int D,
                      const float* Wl, const float* Wr, const float* b,
                      float* outbuf, int Nout, int relu)
{
    float* mean;
    cudaGetSymbolAddress((void**)&mean, g_mean);

    int aggBlocks = (n_tgt * 32 + 255) / 256;
    if (D == 128)
        aggregate_kernel<128><<<aggBlocks, 256>>>(X, mean, off, esrc, n_tgt);
    else
        aggregate_kernel<256><<<aggBlocks, 256>>>(X, mean, off, esrc, n_tgt);

    dim3 grid((n_tgt + 127) / 128, Nout / 128);
    sage_gemm_tf32<<<grid, 256>>>(mean, X, Wl, Wr, b, outbuf, n_tgt, Nout, D, relu);
}

extern "C" void kernel_launch(void* const* d_in, const int* in_sizes, int n_in,
                              void* d_out, int out_size)
{
    const float* x    = (const float*)d_in[0];
    const int*   src0 = (const int*)d_in[1];
    const int*   dst0 = (const int*)d_in[2];
    const int*   src1 = (const int*)d_in[3];
    const int*   dst1 = (const int*)d_in[4];
    const int*   src2 = (const int*)d_in[5];
    const int*   dst2 = (const int*)d_in[6];
    const float* wl0  = (const float*)d_in[7];
    const float* wr0  = (const float*)d_in[8];
    const float* b0   = (const float*)d_in[9];
    const float* wl1  = (const float*)d_in[10];
    const float* wr1  = (const float*)d_in[11];
    const float* b1   = (const float*)d_in[12];
    const float* wl2  = (const float*)d_in[13];
    const float* wr2  = (const float*)d_in[14];
    const float* b2   = (const float*)d_in[15];
    float* out = (float*)d_out;

    float *h1, *h2;
    cudaGetSymbolAddress((void**)&h1, g_h1);
    cudaGetSymbolAddress((void**)&h2, g_h2);
    int *off0, *off1, *off2, *es0, *es1, *es2;
    cudaGetSymbolAddress((void**)&off0, g_off0);
    cudaGetSymbolAddress((void**)&off1, g_off1);
    cudaGetSymbolAddress((void**)&off2, g_off2);
    cudaGetSymbolAddress((void**)&es0, g_esrc0);
    cudaGetSymbolAddress((void**)&es1, g_esrc1);
    cudaGetSymbolAddress((void**)&es2, g_esrc2);

    // Batched CSR build for all 3 layers (feature-independent)
    const int NTOT = N1c + N2c + N3c;
    const int ETOT = E0c + E1c + E2c;
    zero3_kernel<<<(NTOT + 255) / 256, 256>>>();
    hist3_kernel<<<(ETOT + 255) / 256, 256>>>(dst0, dst1, dst2);
    scan3_kernel<<<3, 1024>>>();
    bucket3_kernel<<<(ETOT + 255) / 256, 256>>>(src0, dst0, src1, dst1, src2, dst2);

    // Layer 0: x (N0 x 128) -> h1 (N1 x 256), relu
    run_layer(x,  off0, es0, N1c, DINc, wl0, wr0, b0, h1, DHc, 1);
    // Layer 1: h1 (N1 x 256) -> h2 (N2 x 256), relu
    run_layer(h1, off1, es1, N2c, DHc, wl1, wr1, b1, h2, DHc, 1);
    // Layer 2: h2 (N2 x 256) -> out (N3 x 128), no relu
    run_layer(h2, off2, es2, N3c, DHc, wl2, wr2, b2, out, DOUTc, 0);
}